// round 17
// baseline (speedup 1.0000x reference)
#include <cuda_runtime.h>
#include <stdint.h>

#define NROI    65536
#define NCASC   3
#define NBATCH  64
#define NROWS   (NBATCH * NCASC)
#define SLICES  32
#define SLICE_ELEMS (NROI / SLICES)        // 2048
#define SCAN_TPB 128
#define SCAN_WARPS (SCAN_TPB / 32)         // 4
#define WCHUNK  (SLICE_ELEMS / SCAN_WARPS) // 512 elements per warp
#define FIN_TPB 256
#define ROWCAP  256                        // compact candidates per row
#define SPL     (ROWCAP / 32)              // 8 slots per lane in search warps
#define TPOSC   0.995f
#define TNEGC   0.995f
#define BITS_CAND 0x3F7AE148u              // bits(0.98) — safe lower bound
#define BITS_ONE  0x3F800000u              // bits(1.0)  — values strictly below

struct Keys { uint32_t k0[3]; uint32_t k1[3]; };

// per-(row,slice) metadata — written unconditionally every run (no init pass)
__device__ float  g_pmax [NROWS * SLICES];   // max iou per slice
__device__ float  g_pomax[NROWS * SLICES];   // max overlap per slice
__device__ int    g_pelig[NROWS * SLICES];
// compact per-row candidate lists (counters reset by finalize each run)
__device__ int    g_cprow[NROWS];            // zero-init
__device__ int    g_cnrow[NROWS];            // zero-init
__device__ float  g_posv [NROWS * ROWCAP];
__device__ int    g_posi [NROWS * ROWCAP];
__device__ float  g_negu [NROWS * ROWCAP];
__device__ int    g_negj [NROWS * ROWCAP];

__device__ const float c_POS_T[3] = {0.6f, 0.7f, 0.8f};
__device__ const float c_IOU_T[3] = {0.2f, 0.3f, 0.4f};
__device__ const float c_NEG_T[3] = {0.3f, 0.3f, 0.3f};

// ---------------------------------------------------------------------------
// JAX threefry2x32 (exact; verified rel_err = 0.0)
// ---------------------------------------------------------------------------
__host__ __device__ __forceinline__ void threefry2x32(
    uint32_t k0, uint32_t k1, uint32_t x0, uint32_t x1,
    uint32_t& o0, uint32_t& o1)
{
    uint32_t ks2 = k0 ^ k1 ^ 0x1BD11BDAu;
    x0 += k0; x1 += k1;
#define TFR(r) { x0 += x1; x1 = (x1 << (r)) | (x1 >> (32 - (r))); x1 ^= x0; }
    TFR(13) TFR(15) TFR(26) TFR(6)  x0 += k1;  x1 += ks2 + 1u;
    TFR(17) TFR(29) TFR(16) TFR(24) x0 += ks2; x1 += k0  + 2u;
    TFR(13) TFR(15) TFR(26) TFR(6)  x0 += k0;  x1 += k1  + 3u;
    TFR(17) TFR(29) TFR(16) TFR(24) x0 += k1;  x1 += ks2 + 4u;
    TFR(13) TFR(15) TFR(26) TFR(6)  x0 += ks2; x1 += k0  + 5u;
#undef TFR
    o0 = x0; o1 = x1;
}

__device__ __forceinline__ float u01(uint32_t k0, uint32_t k1, uint32_t idx)
{
    uint32_t a, c;
    threefry2x32(k0, k1, 0u, idx, a, c);
    uint32_t bits = a ^ c;
    return __uint_as_float((bits >> 9) | 0x3F800000u) - 1.0f;
}

// ---------------------------------------------------------------------------
// Warp-local kth-largest over SPL register slots/lane (invalid slots = -1).
// Binary search on float bits; counting via __reduce_add_sync. No barriers.
// Exact. Precondition: count(v >= uint_as_float(lo)) >= k.
// ---------------------------------------------------------------------------
__device__ float warp_kth8(int k, const float (&v)[SPL],
                           unsigned lo, unsigned hi)
{
    while (hi > lo) {
        unsigned mid = lo + ((hi - lo + 1u) >> 1);
        float t = __uint_as_float(mid);
        int c = 0;
#pragma unroll
        for (int s = 0; s < SPL; s++) c += (v[s] >= t);
        c = (int)__reduce_add_sync(0xFFFFFFFFu, (unsigned)c);
        if (c >= k) lo = mid; else hi = mid - 1u;
    }
    return __uint_as_float(lo);
}

// top_k[1] semantics: max if multiplicity >= 2, else largest strictly below.
__device__ float warp_top2_8(const float (&v)[SPL])
{
    float m1l = 0.0f;
#pragma unroll
    for (int s = 0; s < SPL; s++) m1l = fmaxf(m1l, v[s]);
    float m1 = __uint_as_float(
        __reduce_max_sync(0xFFFFFFFFu, __float_as_uint(m1l)));
    int c1 = 0;
#pragma unroll
    for (int s = 0; s < SPL; s++) c1 += (v[s] >= m1);
    c1 = (int)__reduce_add_sync(0xFFFFFFFFu, (unsigned)c1);
    if (c1 >= 2) return m1;
    float m2l = 0.0f;
#pragma unroll
    for (int s = 0; s < SPL; s++) m2l = fmaxf(m2l, (v[s] < m1) ? v[s] : 0.0f);
    return __uint_as_float(
        __reduce_max_sync(0xFFFFFFFFu, __float_as_uint(m2l)));
}

// ---------------------------------------------------------------------------
// Exact full-row fallbacks (statistically never run). 256-thread block.
// ---------------------------------------------------------------------------
__device__ __forceinline__ int block_sum256(int c, int* s_ws)
{
    c = (int)__reduce_add_sync(0xFFFFFFFFu, (unsigned)c);
    if ((threadIdx.x & 31) == 0) s_ws[threadIdx.x >> 5] = c;
    __syncthreads();
    int tot = 0;
#pragma unroll
    for (int w = 0; w < FIN_TPB / 32; w++) tot += s_ws[w];
    __syncthreads();
    return tot;
}

__device__ __noinline__ float kth_bs_iomask(int k, const float* ov,
                                            const float* io, float POS_T,
                                            int nopos, float mx, int* s_ws)
{
    unsigned lo = 0u, hi = 0x7F800000u;
    while (hi > lo) {
        unsigned mid = lo + ((hi - lo + 1u) >> 1);
        float t = __uint_as_float(mid);
        int c = 0;
        for (int j = threadIdx.x; j < NROI; j += FIN_TPB) {
            float o = ov[j], v = io[j];
            float im = nopos ? ((v >= mx) ? v : 0.0f)
                             : ((o >= POS_T) ? v : 0.0f);
            c += (im >= t);
        }
        c = block_sum256(c, s_ws);
        if (c >= k) lo = mid; else hi = mid - 1u;
    }
    return __uint_as_float(lo);
}

__device__ __noinline__ float kth_bs_score(int k, const float* ov, float NEG_T,
                                           uint32_t k0, uint32_t k1,
                                           uint32_t rng_base, int* s_ws)
{
    unsigned lo = 0u, hi = 0x7F800000u;
    while (hi > lo) {
        unsigned mid = lo + ((hi - lo + 1u) >> 1);
        float t = __uint_as_float(mid);
        int c = 0;
        for (int j = threadIdx.x; j < NROI; j += FIN_TPB) {
            float o = ov[j];
            if (o <= NEG_T) {
                float u = u01(k0, k1, rng_base + (uint32_t)j);
                c += (u >= t);
            }
        }
        c = block_sum256(c, s_ws);
        if (c >= k) lo = mid; else hi = mid - 1u;
    }
    return __uint_as_float(lo);
}

// ---------------------------------------------------------------------------
// Kernel A: scan + default-fill. grid = NROWS*SLICES = 6144 blocks, 128 thr.
// Candidates push to compact per-row global lists (row counters).
// ---------------------------------------------------------------------------
__global__ __launch_bounds__(SCAN_TPB)
void scan_kernel(const float* __restrict__ g_ov,
                 const float* __restrict__ g_io,
                 float* __restrict__ g_out,
                 Keys keys)
{
    __shared__ uint16_t s_q[SCAN_WARPS][WCHUNK];   // 4 KB
    __shared__ float s_wmax[SCAN_WARPS];
    __shared__ float s_womax[SCAN_WARPS];
    __shared__ int   s_welig[SCAN_WARPS];

    const int tid   = threadIdx.x;
    const int wid   = tid >> 5;
    const int lane  = tid & 31;
    const int blk   = blockIdx.x;
    const int r     = blk >> 5;
    const int slice = blk & (SLICES - 1);
    const int h     = r % 3;
    const int b     = r / 3;

    const float POS_T = c_POS_T[h];
    const float NEG_T = c_NEG_T[h];
    const uint32_t k0 = keys.k0[h];
    const uint32_t k1 = keys.k1[h];
    const uint32_t rng_base = (uint32_t)b * (uint32_t)NROI;

    const int chunk0 = slice * SLICE_ELEMS + wid * WCHUNK;
    const float4* ov4 = (const float4*)(g_ov + (size_t)r * NROI) + (chunk0 >> 2);
    const float4* io4 = (const float4*)(g_io + (size_t)r * NROI) + (chunk0 >> 2);
    float4* out4 = (float4*)(g_out + (size_t)r * NROI) + (chunk0 >> 2);
    const float4 NEG1 = make_float4(-1.0f, -1.0f, -1.0f, -1.0f);

    const unsigned lmask = (1u << lane) - 1u;
    float lmax = 0.0f;     // max iou
    float lomax = 0.0f;    // max overlap  (poscnt>0  <=>  lomax >= POS_T)
    int cnt = 0;

    // ---------- Phase A: scan + compact + default-fill ----------
#pragma unroll
    for (int it = 0; it < WCHUNK / 4 / 32; it++) {   // 4 iters
        int q = it * 32 + lane;
        float4 o4 = __ldcs(&ov4[q]);
        float4 v4 = __ldcs(&io4[q]);
        __stcs(&out4[q], NEG1);                      // default label
        int local = q * 4;
#pragma unroll
        for (int l = 0; l < 4; l++) {
            float o = (&o4.x)[l];
            float v = (&v4.x)[l];
            lmax = fmaxf(lmax, v);
            lomax = fmaxf(lomax, o);
            if (v >= TPOSC && o >= POS_T) {          // ~0.2% of elements
                int p = atomicAdd(&g_cprow[r], 1);
                if (p < ROWCAP) {
                    g_posv[r * ROWCAP + p] = v;
                    g_posi[r * ROWCAP + p] = chunk0 + local + l;
                }
            }
            bool el = (o <= NEG_T);
            unsigned m = __ballot_sync(0xFFFFFFFFu, el);
            if (el) s_q[wid][cnt + __popc(m & lmask)] = (uint16_t)(local + l);
            cnt += __popc(m);
        }
    }
    __syncwarp();

    // ---------- Phase B: dense hashing of compacted queue ----------
    const uint32_t jwbase = rng_base + (uint32_t)chunk0;
    for (int t = lane; t < cnt; t += 32) {
        uint32_t idx = (uint32_t)s_q[wid][t];
        float u = u01(k0, k1, jwbase + idx);
        if (u >= TNEGC) {                            // ~0.5% of eligible
            int p = atomicAdd(&g_cnrow[r], 1);
            if (p < ROWCAP) {
                g_negu[r * ROWCAP + p] = u;
                g_negj[r * ROWCAP + p] = (int)(chunk0 + idx);
            }
        }
    }

    // ---------- reductions ----------
    unsigned wmaxb  = __reduce_max_sync(0xFFFFFFFFu, __float_as_uint(lmax));
    unsigned womaxb = __reduce_max_sync(0xFFFFFFFFu, __float_as_uint(lomax));
    if (lane == 0) {
        s_wmax[wid]  = __uint_as_float(wmaxb);
        s_womax[wid] = __uint_as_float(womaxb);
        s_welig[wid] = cnt;
    }
    __syncthreads();
    if (tid == 0) {
        float mx = 0.0f, omx = 0.0f; int ec = 0;
#pragma unroll
        for (int w = 0; w < SCAN_WARPS; w++) {
            mx = fmaxf(mx, s_wmax[w]);
            omx = fmaxf(omx, s_womax[w]);
            ec += s_welig[w];
        }
        g_pmax[blk] = mx;
        g_pomax[blk] = omx;
        g_pelig[blk] = ec;
    }
}

// ---------------------------------------------------------------------------
// Kernel B: per-row finalize + scatter. grid = NROWS, 256 threads.
// Compact candidates: 1 slot/thread load, 8 slots/lane searches on 3 warps.
// ---------------------------------------------------------------------------
__global__ __launch_bounds__(FIN_TPB)
void finalize_kernel(const float* __restrict__ g_ov,
                     const float* __restrict__ g_io,
                     const float* __restrict__ g_nm,
                     float* __restrict__ g_out,
                     Keys keys)
{
    __shared__ float s_pv[ROWCAP];
    __shared__ float s_nu[ROWCAP];
    __shared__ int   s_eligs[SLICES];
    __shared__ float s_mxs[SLICES], s_omxs[SLICES];
    __shared__ float s_tk, s_top2, s_kth;
    __shared__ int   s_cnt2[2];
    __shared__ int   s_ws[FIN_TPB / 32];     // slow-path reduce scratch

    const int tid = threadIdx.x;
    const int wid = tid >> 5;
    const int lane = tid & 31;
    const int r = blockIdx.x;
    const int h = r % 3;
    const int b = r / 3;

    const float POS_T = c_POS_T[h];
    const float NEG_T = c_NEG_T[h];
    const float IOU_T = c_IOU_T[h];
    const uint32_t k0 = keys.k0[h];
    const uint32_t k1 = keys.k1[h];
    const uint32_t rng_base = (uint32_t)b * (uint32_t)NROI;

    const float* ov = g_ov + (size_t)r * NROI;
    const float* io = g_io + (size_t)r * NROI;
    const float* nm = g_nm + (size_t)r * NROI;
    float*       out = g_out + (size_t)r * NROI;

    // ---- metadata + candidate loads issued together ----
    if (tid < SLICES) {
        int blk = r * SLICES + tid;
        s_eligs[tid]= g_pelig[blk];
        s_mxs[tid]  = g_pmax[blk];
        s_omxs[tid] = g_pomax[blk];
    }
    if (tid == 0) {
        s_cnt2[0] = g_cprow[r];
        s_cnt2[1] = g_cnrow[r];
        g_cprow[r] = 0;                  // reset for next graph replay
        g_cnrow[r] = 0;
    }
    float pv = g_posv[r * ROWCAP + tid];     // speculative; masked below
    int   pj = g_posi[r * ROWCAP + tid];
    float nu = g_negu[r * ROWCAP + tid];
    int   nj = g_negj[r * ROWCAP + tid];
    __syncthreads();                                   // barrier 1

    const int cp = s_cnt2[0];
    const int cn = s_cnt2[1];
    float mx = 0.0f, omx = 0.0f;
    int eligcnt = 0;
#pragma unroll
    for (int s = 0; s < SLICES; s++) {
        mx = fmaxf(mx, s_mxs[s]); omx = fmaxf(omx, s_omxs[s]);
        eligcnt += s_eligs[s];
    }
    if (tid >= cp) pv = -1.0f;               // mask invalid slots
    if (tid >= cn) nu = -1.0f;

    const int nopos = (omx < POS_T);     // poscnt == 0  <=>  max(ov) < POS_T
    const bool fast = (!nopos) && cp >= 16 && cp <= ROWCAP &&
                      (eligcnt >= 48) && cn >= 48 && cn <= ROWCAP;

    if (fast) {
        s_pv[tid] = pv;
        s_nu[tid] = nu;
        __syncthreads();                               // barrier 2

        // three order statistics on three warps, concurrently, barrier-free
        if (wid < 3) {
            float v[SPL];
#pragma unroll
            for (int s = 0; s < SPL; s++)
                v[s] = (wid == 2) ? s_nu[s * 32 + lane] : s_pv[s * 32 + lane];
            if (wid == 0) {
                float t16 = warp_kth8(16, v, BITS_CAND, BITS_ONE);
                if (lane == 0) s_tk = (t16 >= IOU_T) ? t16 : IOU_T;
            } else if (wid == 1) {
                float t2 = (h == 0) ? warp_top2_8(v) : 0.0f;
                if (lane == 0) s_top2 = t2;
            } else {
                float kth = warp_kth8(48, v, BITS_CAND, BITS_ONE);
                if (lane == 0) s_kth = kth;
            }
        }
        __syncthreads();                               // barrier 3

        const float tk = s_tk, top2 = s_top2, kth = s_kth;
        // scatter the ~65 differing labels over the -1 default (1 slot/thread)
        if (nu >= kth)
            out[nj] = 0.0f;                  // -1 + 1; disjoint from pos
        bool posb = (pv >= tk) || (h == 0 && pv > top2);
        if (posb)                            // invalid (-1) never selects
            out[pj] = -1.0f + 2.0f * nm[pj];
        return;
    }

    // ---------------- slow path: rewrite whole row exactly ----------------
    float t16 = kth_bs_iomask(16, ov, io, POS_T, nopos, mx, s_ws);
    float top2 = 0.0f;
    if (h == 0) top2 = kth_bs_iomask(2, ov, io, POS_T, nopos, mx, s_ws);
    float tk = (t16 >= IOU_T) ? t16 : IOU_T;

    float kth = -1.0f;
    int allelig = (eligcnt < 48);
    if (!allelig)
        kth = kth_bs_score(48, ov, NEG_T, k0, k1, rng_base, s_ws);

    const float4* ov4 = (const float4*)ov;
    const float4* io4 = (const float4*)io;
    float4* out4 = (float4*)out;
    for (int q = tid; q < NROI / 4; q += FIN_TPB) {
        float4 o4 = ov4[q];
        float4 v4 = io4[q];
        float4 res;
#pragma unroll
        for (int l = 0; l < 4; l++) {
            int j = q * 4 + l;
            float o = (&o4.x)[l];
            float v = (&v4.x)[l];
            float im = nopos ? ((v >= mx) ? v : 0.0f)
                             : ((o >= POS_T) ? v : 0.0f);
            bool posb = (im >= tk);
            if (h == 0) posb = posb || (im > top2);
            float posf = 0.0f;
            if (posb) posf = nm[j];

            float negf = 0.0f;
            if (o <= NEG_T) {
                if (allelig) negf = 1.0f;
                else {
                    float u = u01(k0, k1, rng_base + (uint32_t)j);
                    if (u >= kth) negf = 1.0f;
                }
            }
            (&res.x)[l] = (-1.0f + negf) + 2.0f * posf;
        }
        out4[q] = res;
    }
}

// ---------------------------------------------------------------------------
// Launch
// ---------------------------------------------------------------------------
extern "C" void kernel_launch(void* const* d_in, const int* in_sizes, int n_in,
                              void* d_out, int out_size)
{
    const float* ov = (const float*)d_in[0];
    const float* io = (const float*)d_in[1];
    const float* nm = (const float*)d_in[2];
    float* out = (float*)d_out;

    Keys keys;
    for (int h = 0; h < NCASC; h++) {
        uint32_t a, c;
        threefry2x32(0u, 42u, 0u, (uint32_t)h, a, c);
        keys.k0[h] = a;
        keys.k1[h] = c;
    }

    scan_kernel<<<NROWS * SLICES, SCAN_TPB>>>(ov, io, out, keys);
    finalize_kernel<<<NROWS, FIN_TPB>>>(ov, io, nm, out, keys);
}